// round 12
// baseline (speedup 1.0000x reference)
#include <cuda_runtime.h>
#include <cuda_bf16.h>

#define RX   128
#define DD   64
#define NBU  32
#define NTILE (NBU*RX)   // 4096

// Scratch
__device__ float g_P[NBU*RX*DD];
__device__ float g_B[NBU*RX*DD];
__device__ float g_G[NBU*RX*DD];
__device__ float g_S[NBU*RX*RX];       // <P_i,B_j>
__device__ float g_stats[NBU*RX*8];    // sumP,sumP2,sumB,sumB2,sumG,sumG2,sPG,sBG
__device__ float g_pm[NBU*DD];         // b1 + W1[:,256:320]@m
__device__ float g_gm[NBU*DD];         // W1[:,192:256]@m

typedef unsigned int u32;

__device__ __forceinline__ u32 smem_u32(const void* p) {
    u32 a;
    asm("{ .reg .u64 t; cvta.to.shared.u64 t, %1; cvt.u32.u64 %0, t; }" : "=r"(a) : "l"(p));
    return a;
}

// -------------------------------------------------------------------------
// Kernel 0: per-bu mean + pm/gm. grid = NBU, 256 threads.
// -------------------------------------------------------------------------
__global__ void __launch_bounds__(256) mean_kernel(
    const float* __restrict__ x, const float* __restrict__ W1,
    const float* __restrict__ b1)
{
    __shared__ float msp[4][DD];
    __shared__ float mm[DD];

    const int bu = blockIdx.x;
    const int t  = threadIdx.x;
    const float* xp = x + (size_t)bu * RX * DD;

    {
        const int col = t & 63;
        const int q   = t >> 6;
        float s = 0.f;
        #pragma unroll 8
        for (int r = q*32; r < q*32 + 32; r++) s += xp[(size_t)r*DD + col];
        msp[q][col] = s;
    }
    __syncthreads();
    if (t < DD)
        mm[t] = (msp[0][t] + msp[1][t] + msp[2][t] + msp[3][t]) * (1.f / RX);
    __syncthreads();

    const int o  = t >> 2;
    const int kq = t & 3;
    float pv = 0.f, gv = 0.f;
    #pragma unroll
    for (int s = 0; s < 16; s++) {
        const int k = kq*16 + s;
        const float mv = mm[k];
        gv += W1[(size_t)o*320 + 192 + k] * mv;
        pv += W1[(size_t)o*320 + 256 + k] * mv;
    }
    pv += __shfl_xor_sync(0xffffffffu, pv, 1);
    gv += __shfl_xor_sync(0xffffffffu, gv, 1);
    pv += __shfl_xor_sync(0xffffffffu, pv, 2);
    gv += __shfl_xor_sync(0xffffffffu, gv, 2);
    if (kq == 0) {
        g_pm[bu*DD + o] = b1[o] + pv;
        g_gm[bu*DD + o] = gv;
    }
}

// -------------------------------------------------------------------------
// Kernel 1: P,B,G rows + per-row stats. grid = (NBU, 8), 512 thr.
// -------------------------------------------------------------------------
#define PREP_SMEM_FLOATS (3*4096 + 16*68 + 3*16*65 + 2*64)
#define PREP_SMEM_BYTES  (PREP_SMEM_FLOATS*4)

__global__ void __launch_bounds__(512) prep_kernel(
    const float* __restrict__ x, const float* __restrict__ W1)
{
    extern __shared__ float sm[];
    float* ws  = sm;                    // [3][64][64]
    float* xs  = ws + 3*4096;           // [16][68]
    float* sP  = xs + 16*68;            // [16][65]
    float* sB  = sP + 16*65;
    float* sG  = sB + 16*65;
    float* pms = sG + 16*65;            // [64]
    float* gms = pms + 64;              // [64]

    const int bu  = blockIdx.x;
    const int ic0 = blockIdx.y * 16;
    const int t   = threadIdx.x;
    const int wid = t >> 5, lane = t & 31;

    const float* xp = x + (size_t)bu * RX * DD;

    for (int i4 = t; i4 < 3*1024; i4 += 512) {
        const int blk = i4 >> 10;
        const int rem = i4 & 1023;
        const int o = rem >> 4, k4 = rem & 15;
        const float4 v = *(const float4*)(W1 + (size_t)o*320 + blk*64 + k4*4);
        *(float4*)(ws + blk*4096 + o*64 + k4*4) = v;
    }
    if (t < 256) {
        const int r = t >> 4, c4 = t & 15;
        const float4 v = *(const float4*)(xp + (size_t)(ic0 + r)*DD + c4*4);
        *(float4*)(xs + r*68 + c4*4) = v;
    }
    if (t >= 256 && t < 320) pms[t-256] = g_pm[bu*DD + (t-256)];
    if (t >= 320 && t < 384) gms[t-320] = g_gm[bu*DD + (t-320)];
    __syncthreads();

    #pragma unroll
    for (int s = 0; s < 2; s++) {
        const int il = lane & 15;
        const int o  = wid*4 + (lane >> 4)*2 + s;
        const float4* xi = (const float4*)(xs + il*68);
        const float4* wa = (const float4*)(ws + 0*4096 + o*64);
        const float4* wb = (const float4*)(ws + 1*4096 + o*64);
        const float4* wc = (const float4*)(ws + 2*4096 + o*64);
        float accP = pms[o], accB = 0.f, accG = gms[o];
        #pragma unroll
        for (int k4 = 0; k4 < 16; k4++) {
            const float4 xv = xi[k4];
            const float4 a = wa[k4];
            const float4 b = wb[k4];
            const float4 c = wc[k4];
            accG += xv.x*a.x + xv.y*a.y + xv.z*a.z + xv.w*a.w;
            accP += xv.x*b.x + xv.y*b.y + xv.z*b.z + xv.w*b.w;
            accB += xv.x*c.x + xv.y*c.y + xv.z*c.z + xv.w*c.w;
        }
        const int off = (bu*RX + ic0 + il)*DD + o;
        g_P[off] = accP;
        g_B[off] = accB;
        g_G[off] = accG;
        sP[il*65 + o] = accP;
        sB[il*65 + o] = accB;
        sG[il*65 + o] = accG;
    }
    __syncthreads();

    {
        const int row = wid;
        const float p0 = sP[row*65 + lane], p1 = sP[row*65 + lane+32];
        const float b0 = sB[row*65 + lane], b1v = sB[row*65 + lane+32];
        const float q0 = sG[row*65 + lane], q1 = sG[row*65 + lane+32];
        float v0 = p0 + p1;
        float v1 = p0*p0 + p1*p1;
        float v2 = b0 + b1v;
        float v3 = b0*b0 + b1v*b1v;
        float v4 = q0 + q1;
        float v5 = q0*q0 + q1*q1;
        float v6 = p0*q0 + p1*q1;
        float v7 = b0*q0 + b1v*q1;
        #pragma unroll
        for (int m = 16; m > 0; m >>= 1) {
            v0 += __shfl_xor_sync(0xffffffffu, v0, m);
            v1 += __shfl_xor_sync(0xffffffffu, v1, m);
            v2 += __shfl_xor_sync(0xffffffffu, v2, m);
            v3 += __shfl_xor_sync(0xffffffffu, v3, m);
            v4 += __shfl_xor_sync(0xffffffffu, v4, m);
            v5 += __shfl_xor_sync(0xffffffffu, v5, m);
            v6 += __shfl_xor_sync(0xffffffffu, v6, m);
            v7 += __shfl_xor_sync(0xffffffffu, v7, m);
        }
        if (lane == 0) {
            float* so = g_stats + (size_t)(bu*RX + ic0 + row)*8;
            so[0]=v0; so[1]=v1; so[2]=v2; so[3]=v3; so[4]=v4; so[5]=v5; so[6]=v6; so[7]=v7;
        }
    }
}

// -------------------------------------------------------------------------
// Kernel 2: S[bu][i][j] = <P_i, B_j>. grid = (NBU, 4), 256 threads.
// -------------------------------------------------------------------------
__global__ void __launch_bounds__(256) spb_kernel()
{
    const int bu  = blockIdx.x;
    const int ic0 = blockIdx.y * 32;

    __shared__ float Ps[32*68];
    __shared__ float Bs[RX*68];

    const float* Pb = g_P + (size_t)(bu*RX + ic0)*DD;
    for (int t = threadIdx.x; t < 32*DD; t += 256) {
        int r = t >> 6, c = t & 63;
        Ps[r*68 + c] = Pb[t];
    }
    const float* Bb = g_B + (size_t)bu*RX*DD;
    for (int t = threadIdx.x; t < RX*DD; t += 256) {
        int r = t >> 6, c = t & 63;
        Bs[r*68 + c] = Bb[t];
    }
    __syncthreads();

    const int il = threadIdx.x & 31;
    const int jb = threadIdx.x >> 5;
    const float4* pr = (const float4*)(Ps + il*68);
    float* so = g_S + ((size_t)(bu*RX) + ic0 + il)*RX + jb*16;
    #pragma unroll 1
    for (int jo = 0; jo < 16; jo++) {
        const float4* br = (const float4*)(Bs + (jb*16 + jo)*68);
        float a0 = 0.f, a1 = 0.f, a2 = 0.f, a3 = 0.f;
        #pragma unroll
        for (int k4 = 0; k4 < 16; k4++) {
            const float4 p = pr[k4];
            const float4 b = br[k4];
            a0 += p.x*b.x; a1 += p.y*b.y; a2 += p.z*b.z; a3 += p.w*b.w;
        }
        so[jo] = (a0 + a2) + (a1 + a3);
    }
}

// -------------------------------------------------------------------------
// Kernel 3: HMMA main, A fragments computed IN PLACE (no smem round trip,
// no ldmatrix, no producer shuffles). B frags interleaved uint4 in smem.
// -------------------------------------------------------------------------
#define SM_B2    0
#define SM_BFR   256                    // [4][8][32] uint4 = 16KB
#define SM_TOTAL (256 + 16384)

__device__ __forceinline__ void mma_bf16(
    float &c0, float &c1, float &c2, float &c3,
    u32 a0, u32 a1, u32 a2, u32 a3, u32 b0, u32 b1)
{
    asm volatile(
        "mma.sync.aligned.m16n8k16.row.col.f32.bf16.bf16.f32 "
        "{%0,%1,%2,%3}, {%4,%5,%6,%7}, {%8,%9}, {%0,%1,%2,%3};"
        : "+f"(c0), "+f"(c1), "+f"(c2), "+f"(c3)
        : "r"(a0), "r"(a1), "r"(a2), "r"(a3), "r"(b0), "r"(b1));
}
__device__ __forceinline__ u32 bf2_u32(float a, float b) {
    __nv_bfloat162 h = __floats2bfloat162_rn(a, b);
    return *(u32*)&h;
}
// pack y0,y1 -> hi u32; residuals -> lo u32
__device__ __forceinline__ void split2(float y0, float y1, u32 &hi, u32 &lo) {
    __nv_bfloat162 h = __floats2bfloat162_rn(y0, y1);
    hi = *(u32*)&h;
    lo = bf2_u32(y0 - __bfloat162float(h.x), y1 - __bfloat162float(h.y));
}

#define MAIN_PER  14
#define MAIN_GRID ((NTILE + MAIN_PER - 1) / MAIN_PER)   // 293

__global__ void __launch_bounds__(256, 2) main_mma(
    const float* __restrict__ ln_g, const float* __restrict__ ln_b,
    const float* __restrict__ bias, const float* __restrict__ W2,
    const float* __restrict__ b2,   float* __restrict__ out)
{
    extern __shared__ char smem[];
    const int t    = threadIdx.x;
    const int wid  = t >> 5;
    const int lane = t & 31;
    const int g    = lane >> 2;
    const int t4   = lane & 3;

    float* b2s = (float*)(smem + SM_B2);
    uint4* Bfr = (uint4*)(smem + SM_BFR);   // [ks][nt][lane] = {bh.x,bh.y,bl.x,bl.y}

    if (t < DD) b2s[t] = b2[t];

    for (int s = t; s < 4*8*32; s += 256) {
        const int ls = s & 31, nt = (s >> 5) & 7, ks = s >> 8;
        const int o  = nt*8 + (ls >> 2);
        const int d  = ks*16 + (ls & 3)*2;
        const float* w = W2 + (size_t)o*DD + d;
        float w0 = w[0], w1 = w[1], w8 = w[8], w9 = w[9];
        __nv_bfloat16 h0 = __float2bfloat16(w0), h1 = __float2bfloat16(w1);
        __nv_bfloat16 h8 = __float2bfloat16(w8), h9 = __float2bfloat16(w9);
        uint4 bf;
        bf.x = ((u32)*(unsigned short*)&h0) | ((u32)*(unsigned short*)&h1 << 16);
        bf.y = ((u32)*(unsigned short*)&h8) | ((u32)*(unsigned short*)&h9 << 16);
        bf.z = bf2_u32(w0 - __bfloat162float(h0), w1 - __bfloat162float(h1));
        bf.w = bf2_u32(w8 - __bfloat162float(h8), w9 - __bfloat162float(h9));
        Bfr[(ks*8 + nt)*32 + ls] = bf;
    }
    __syncthreads();

    // rows owned by this thread's A fragment
    const int r0 = wid*16 + g;
    const int r1 = r0 + 8;

    // hoist LN params at this thread's 16 columns: [ks][0..3] = cols
    // {ks*16+2t4, +1, ks*16+8+2t4, +1}
    float lgv[16], lbv[16];
    #pragma unroll
    for (int ks = 0; ks < 4; ks++) {
        const int c0 = ks*16 + 2*t4;
        const float2 a0 = *(const float2*)(ln_g + c0);
        const float2 a1 = *(const float2*)(ln_g + c0 + 8);
        const float2 b0 = *(const float2*)(ln_b + c0);
        const float2 b1 = *(const float2*)(ln_b + c0 + 8);
        lgv[ks*4+0] = a0.x; lgv[ks*4+1] = a0.y; lgv[ks*4+2] = a1.x; lgv[ks*4+3] = a1.y;
        lbv[ks*4+0] = b0.x; lbv[ks*4+1] = b0.y; lbv[ks*4+2] = b1.x; lbv[ks*4+3] = b1.y;
    }

    const int tile0 = blockIdx.x * MAIN_PER;
    const int tile1 = (tile0 + MAIN_PER < NTILE) ? (tile0 + MAIN_PER) : NTILE;

    for (int tile = tile0; tile < tile1; tile++) {
        const int bu = tile >> 7;
        const int i  = tile & 127;
        const size_t row = (size_t)bu*RX + i;
        const float* st = g_stats + (size_t)bu*RX*8;
        const float* Pi = g_P + row*DD;
        const float* Br0 = g_B + ((size_t)bu*RX + r0)*DD;
        const float* Br1 = g_B + ((size_t)bu*RX + r1)*DD;

        // LN scalars for rows r0, r1 (no reductions)
        const float2 spi = *(const float2*)(st + i*8);
        const float2 sb0 = *(const float2*)(st + r0*8 + 2);
        const float2 sb1 = *(const float2*)(st + r1*8 + 2);
        const float S0 = g_S[row*RX + r0];
        const float S1 = g_S[row*RX + r1];
        float sum0 = spi.x + sb0.x, e20 = spi.y + sb0.y + 2.f*S0;
        float sum1 = spi.x + sb1.x, e21 = spi.y + sb1.y + 2.f*S1;
        const bool dg0 = (r0 == i);
        const bool dg1 = (r1 == i);
        if (dg0 | dg1) {
            const float4 sdi = *(const float4*)(st + i*8 + 4);
            const float add_s = sdi.x;
            const float add_e = sdi.y + 2.f*(sdi.z + sdi.w);
            if (dg0) { sum0 += add_s; e20 += add_e; }
            else     { sum1 += add_s; e21 += add_e; }
        }
        const float mu0 = sum0*(1.f/64.f);
        const float rs0 = rsqrtf(e20*(1.f/64.f) - mu0*mu0 + 1e-5f);
        const float mu1 = sum1*(1.f/64.f);
        const float rs1 = rsqrtf(e21*(1.f/64.f) - mu1*mu1 + 1e-5f);

        // A fragments: per ks, cols c0,c0+1 (frag 0/1) and c0+8,c0+9 (frag 2/3)
        u32 ah[4][4], al[4][4];
        #pragma unroll
        for (int ks = 0; ks < 4; ks++) {
            const int c0 = ks*16 + 2*t4;
            const float2 p0 = *(const float2*)(Pi + c0);
            const float2 p2 = *(const float2*)(Pi + c0 + 8);
            const float2 b00 = *(const float2*)(Br0 + c0);
            const float2 b02 = *(const float2*)(Br0 + c0 + 8);
            const float2 b10 = *(const float2*)(Br1 + c0);
            const float2 b12 = *(const float2*)(Br1 + c0 + 8);

            float h00x = p0.x + b00.x, h00y = p0.y + b00.y;   // row r0, c0/c0+1
            float h02x = p2.x + b02.x, h02y = p2.y + b02.y;   // row r0, c0+8/+9
            float h10x = p0.x + b10.x, h10y = p0.y + b10.y;   // row r1
            float h12x = p2.x + b12.x, h12y = p2.y + b12.y;

            float bi0x = 0.f, bi0y = 0.f, bi2x = 0.f, bi2y = 0.f;
            if (dg0 | dg1) {
                const float2 gv0 = *(const float2*)(g_G + row*DD + c0);
                const float2 gv2 = *(const float2*)(g_G + row*DD + c0 + 8);
                const float2 bv0 = *(const float2*)(bias + c0);
                const float2 bv2 = *(const float2*)(bias + c0 + 8);
                if (dg0) { h00x += gv0.x; h00y += gv0.y; h02x += gv2.x; h02y += gv2.y; }
                else     { h10x += gv0.x; h10y += gv0.y; h12x += gv2.x; h12y += gv2.y; }
                bi0x = bv0.x; bi0y = bv0.y; bi2x = bv2.x; bi2y = bv2.y;
            }

            const float lg0x = lgv[ks*4+0], lg0y = lgv[ks*4+1];
            const float lg2x = lgv[ks*4+2], lg2y = lgv[ks*4+3];
            const float lb0x = lbv[ks*4+0], lb0y = lbv[ks*4+1];
            const float lb2x = lbv[ks*4+2], lb2y = lbv[ks*4+3];

            float y00x = fmaxf(fmaf((h00x - mu0)*rs0, lg0x, lb0x), 0.f);
            float y00y = fmaxf(fmaf((h00y - mu0)*rs0, lg0y, lb0y), 0.f);
            float y02x = fmaxf(fmaf((h02x - mu0)*rs0, lg2x, lb2x), 0.f);
            float y02y = fmaxf(fmaf((h02y - mu0)*rs0, lg2y, lb2y), 0.f);
            float y10x = fmaxf(fmaf((h10x - mu1)*rs1, lg0x, lb0x), 0.f);
            float y10y = fmaxf(fmaf((h10y - mu1)*rs1, lg0y, lb0y), 0.f);
            float y12x = fmaxf(fmaf((h12x - mu1)*rs1, lg2x, lb2x), 0.f);
            float y12y = fmaxf(fmaf((h12y - mu1)*rs1, lg2y, lb2y), 0.f);
            if (dg0) { y00x += bi0x; y00y += bi0y; y02x += bi2x; y02y += bi2y; }
            if (dg1) { y10x += bi0x; y10y += bi0y; y12x += bi2x; y12y += bi2y; }

            split2(y00x, y00y, ah[ks][0], al[ks][0]);
            split2(y10x, y10y, ah[ks][1], al[ks][1]);
            split2(y02x, y02y, ah[ks][2], al[ks][2]);
            split2(y12x, y12y, ah[ks][3], al[ks][3]);
        }

        // MMA + epilogue
        float* obase = out + row*RX*DD;
        #pragma unroll
        for (int nt = 0; nt < 8; nt++) {
            float c0 = 0.f, c1 = 0.f, c2 = 0.f, c3 = 0.f;
            #pragma unroll
            for (int ks = 0; ks < 4; ks++) {
                const uint4 bf = Bfr[(ks*8 + nt)*32 + lane];
                mma_bf16(c0,c1,c2,c3, ah[ks][0],ah[ks][1],ah[ks][2],ah[ks][3], bf.x, bf.y);
                mma_bf16(c0,c1,c2,c3, ah[ks][0],ah[ks][1],ah[ks][2],ah[ks][3], bf.z, bf.w);
                mma_bf16(c0,c1,c2,c3, al[ks][0],al[ks][1],al[ks][2],al[ks][3], bf.x, bf.y);
            }
            const int o0 = nt*8 + t4*2;
            const float2 bb = *(const float2*)(b2s + o0);
            float2 v0; v0.x = c0 + bb.x; v0.y = c1 + bb.y;
            float2 v1; v1.x = c2 + bb.x; v1.y = c3 + bb.y;
            *(float2*)(obase + (size_t)r0*DD + o0) = v0;
            *(float2*)(obase + (size_t)r1*DD + o0) = v1;
        }
    }
}

// -------------------------------------------------------------------------
// Inputs (metadata order): x, W1, b1, ln_g, ln_b, bias, W2, b2
// -------------------------------------------------------------------------
extern "C" void kernel_launch(void* const* d_in, const int* in_sizes, int n_in,
                              void* d_out, int out_size)
{
    const float* x    = (const float*)d_in[0];
    const float* W1   = (const float*)d_in[1];
    const float* b1   = (const float*)d_in[2];
    const float* ln_g = (const float*)d_in[3];
    const float* ln_b = (const float*)d_in[4];
    const float* bias = (const float*)d_in[5];
    const float* W2   = (const float*)d_in[6];
    const float* b2   = (const float*)d_in[7];
    float* out = (float*)d_out;
    (void)in_sizes; (void)n_in; (void)out_size;

    cudaFuncSetAttribute(prep_kernel, cudaFuncAttributeMaxDynamicSharedMemorySize, PREP_SMEM_BYTES);
    cudaFuncSetAttribute(main_mma, cudaFuncAttributeMaxDynamicSharedMemorySize, SM_TOTAL);

    mean_kernel<<<NBU, 256>>>(x, W1, b1);
    prep_kernel<<<dim3(NBU, 8), 512, PREP_SMEM_BYTES>>>(x, W1);
    spb_kernel<<<dim3(NBU, 4), 256>>>();
    main_mma<<<MAIN_GRID, 256, SM_TOTAL>>>(ln_g, ln_b, bias, W2, b2, out);
}